// round 6
// baseline (speedup 1.0000x reference)
#include <cuda_runtime.h>
#include <cstdint>
#include <cstddef>

#define L_  8
#define M_  128
#define K_  32
#define D_  16
#define B_  2048
#define N_  1024   /* L_*M_ */
#define BT_ 256    /* batch tile per block */

#define XT_OFF   0u
#define TR_OFF   ((unsigned)(D_ * B_))
#define OUT_OFF  ((unsigned)(D_ * B_ + N_ * D_ * B_))

static __device__ float g_scratch[(size_t)D_ * B_ + 2ull * N_ * D_ * B_];

// ---- packed fp32x2 helpers (sm_10x) ---------------------------------------
__device__ __forceinline__ unsigned long long fma2(
    unsigned long long a, unsigned long long b, unsigned long long c)
{
    unsigned long long d;
    asm("fma.rn.f32x2 %0, %1, %2, %3;" : "=l"(d) : "l"(a), "l"(b), "l"(c));
    return d;
}
__device__ __forceinline__ unsigned long long pack2(float lo, float hi)
{
    unsigned long long r;
    asm("mov.b64 %0, {%1, %2};" : "=l"(r) : "f"(lo), "f"(hi));
    return r;
}
__device__ __forceinline__ float2 unpack2(unsigned long long v)
{
    float2 r;
    asm("mov.b64 {%0, %1}, %2;" : "=f"(r.x), "=f"(r.y) : "l"(v));
    return r;
}
__device__ __forceinline__ unsigned smem_u32(const void* p)
{
    unsigned a;
    asm("{ .reg .u64 t; cvta.to.shared.u64 t, %1; cvt.u32.u64 %0, t; }"
        : "=r"(a) : "l"(p));
    return a;
}

// ---------------------------------------------------------------------------
// Transpose: block = (node, half-of-B).  One (1024, D) half-tile -> (D, 1024).
// ---------------------------------------------------------------------------
__global__ void __launch_bounds__(256) transpose_kernel(
    const float* __restrict__ trace, const float* __restrict__ x)
{
    __shared__ float tile[128 * 17];
    const int blk  = blockIdx.x;
    const int half = blockIdx.y;
    const float* src = (blk < N_) ? (trace + (size_t)blk * B_ * D_) : x;
    float* dst = (blk < N_) ? (g_scratch + TR_OFF + (size_t)blk * D_ * B_)
                            : (g_scratch + XT_OFF);
    src += (size_t)half * (B_ / 2) * D_;
    const int t = threadIdx.x;

    for (int ti = 0; ti < B_ / 256; ++ti) {
        const float4* s4 = reinterpret_cast<const float4*>(src + (size_t)ti * 128 * D_);
        #pragma unroll
        for (int j = t; j < 512; j += 256) {
            float4 v = s4[j];
            int bb = j >> 2;
            int dd = (j & 3) * 4;
            tile[bb * 17 + dd + 0] = v.x;
            tile[bb * 17 + dd + 1] = v.y;
            tile[bb * 17 + dd + 2] = v.z;
            tile[bb * 17 + dd + 3] = v.w;
        }
        __syncthreads();
        #pragma unroll
        for (int j = t; j < 2048; j += 256) {
            int d  = j >> 7;
            int bb = j & 127;
            dst[(size_t)d * B_ + half * (B_ / 2) + ti * 128 + bb] = tile[bb * 17 + d];
        }
        __syncthreads();
    }
}

// ---------------------------------------------------------------------------
// Layer kernel: 128 threads, block = (node, 256-batch tile).
//  Phase 1: cp.async-stage all 32 gather rows (32 KB) -- zero-register MLP.
//  Phase 2: thread = (d-half h, 4 batches) computes 32 outputs with packed
//           fp32x2 batch-pair fma2; W pre-duplicated (w,w) in smem so the
//           inner loop is 5 LDS.128 + 16 FFMA2 per k, no packing.
// ---------------------------------------------------------------------------
__global__ void __launch_bounds__(128, 6) layer_kernel(
    float* __restrict__ out,
    const int* __restrict__ src_node,
    const int* __restrict__ src_feat,
    const float* __restrict__ W,
    const float* __restrict__ bias,
    int l)
{
    __shared__ float              sg[K_][BT_];     // staged gathers, 32 KB
    __shared__ unsigned long long sWd[K_ * D_];    // (w,w) duplicated, 4 KB
    __shared__ unsigned long long sBd[D_];         // (bias,bias)
    __shared__ unsigned           sOff[K_];

    const int m = blockIdx.x;
    const int n = l * M_ + m;
    const int t = threadIdx.x;
    const int h  = t >> 6;                 // d-half (warp-coherent)
    const int bg = t & 63;                 // batch group (4 batches)
    const unsigned btile = blockIdx.y * BT_;
    const int b = btile + bg * 4;

    // --- prologue: W (duplicated+transposed), bias, gather offsets ---------
    {
        float4 v = *reinterpret_cast<const float4*>(W + (size_t)n * (D_ * K_) + t * 4);
        int d  = t >> 3;
        int k0 = (t & 7) * 4;
        sWd[(k0 + 0) * D_ + d] = pack2(v.x, v.x);
        sWd[(k0 + 1) * D_ + d] = pack2(v.y, v.y);
        sWd[(k0 + 2) * D_ + d] = pack2(v.z, v.z);
        sWd[(k0 + 3) * D_ + d] = pack2(v.w, v.w);
    }
    if (t < D_) {
        float bb = bias[n * D_ + t];
        sBd[t] = pack2(bb, bb);
    }
    if (t < K_) {
        int sn = src_node[n * K_ + t];
        int sf = src_feat[n * K_ + t];
        unsigned off;
        if (sn == 0) {
            off = XT_OFF + (unsigned)sf * B_;
        } else if (sn <= l * M_) {
            off = OUT_OFF + ((unsigned)(sn - 1) * D_ + (unsigned)sf) * B_;
        } else {
            off = TR_OFF  + ((unsigned)(sn - 1) * D_ + (unsigned)sf) * B_;
        }
        sOff[t] = off;
    }
    __syncthreads();

    // --- phase 1: stage 32 gather rows via cp.async (16 chunks of 16B each)
    #pragma unroll
    for (int j = 0; j < 16; ++j) {
        int idx = j * 128 + t;             // warp-contiguous chunks
        int k = idx >> 6;                  // 64 x 16B chunks per k-row
        int c = (idx & 63) * 4;            // float offset in row
        const float* src = &g_scratch[sOff[k] + btile + (unsigned)c];
        unsigned dst = smem_u32(&sg[k][c]);
        asm volatile("cp.async.cg.shared.global [%0], [%1], 16;\n"
                     :: "r"(dst), "l"(src));
    }
    asm volatile("cp.async.commit_group;\n" ::: "memory");
    asm volatile("cp.async.wait_group 0;\n" ::: "memory");
    __syncthreads();

    // --- phase 2: packed fp32x2 batch-pair GEMV ----------------------------
    // acc[bp][dd]: batch-pair bp in {(b,b+1),(b+2,b+3)}, local d index dd.
    unsigned long long acc[2][8];
    {
        const ulonglong2* bd = reinterpret_cast<const ulonglong2*>(&sBd[h * 8]);
        #pragma unroll
        for (int q = 0; q < 4; ++q) {
            ulonglong2 v = bd[q];
            acc[0][2 * q] = v.x;  acc[0][2 * q + 1] = v.y;
            acc[1][2 * q] = v.x;  acc[1][2 * q + 1] = v.y;
        }
    }

    #pragma unroll
    for (int k = 0; k < K_; ++k) {
        // (g[b],g[b+1]) and (g[b+2],g[b+3]) already packed in the staged row.
        ulonglong2 g2 = *reinterpret_cast<const ulonglong2*>(&sg[k][bg * 4]);
        const ulonglong2* wd = reinterpret_cast<const ulonglong2*>(&sWd[k * D_ + h * 8]);
        #pragma unroll
        for (int q = 0; q < 4; ++q) {      // broadcast LDS.128: 2 dup'd weights
            ulonglong2 w2 = wd[q];
            acc[0][2 * q + 0] = fma2(g2.x, w2.x, acc[0][2 * q + 0]);
            acc[0][2 * q + 1] = fma2(g2.x, w2.y, acc[0][2 * q + 1]);
            acc[1][2 * q + 0] = fma2(g2.y, w2.x, acc[1][2 * q + 0]);
            acc[1][2 * q + 1] = fma2(g2.y, w2.y, acc[1][2 * q + 1]);
        }
    }

    // ReLU + unpack: a[i][dd] = batch b+i, global d = h*8+dd.
    float a[4][8];
    #pragma unroll
    for (int bp = 0; bp < 2; ++bp) {
        #pragma unroll
        for (int dd = 0; dd < 8; ++dd) {
            float2 v = unpack2(acc[bp][dd]);
            a[2 * bp + 0][dd] = fmaxf(v.x, 0.0f);
            a[2 * bp + 1][dd] = fmaxf(v.y, 0.0f);
        }
    }

    // Transposed copy for later-layer gathers (skip on last layer).
    if (l != L_ - 1) {
        float* oT = g_scratch + OUT_OFF + (size_t)n * (D_ * B_) + (size_t)(h * 8) * B_;
        #pragma unroll
        for (int dd = 0; dd < 8; ++dd)
            *reinterpret_cast<float4*>(&oT[dd * B_ + b]) =
                make_float4(a[0][dd], a[1][dd], a[2][dd], a[3][dd]);
    }

    // Final output (N, B, D): per batch, this thread's 8-d half.
    float* o = out + ((size_t)n * B_ + (size_t)b) * D_ + h * 8;
    #pragma unroll
    for (int i = 0; i < 4; ++i) {
        *reinterpret_cast<float4*>(&o[i * D_]) =
            make_float4(a[i][0], a[i][1], a[i][2], a[i][3]);
        *reinterpret_cast<float4*>(&o[i * D_ + 4]) =
            make_float4(a[i][4], a[i][5], a[i][6], a[i][7]);
    }
}

extern "C" void kernel_launch(void* const* d_in, const int* in_sizes, int n_in,
                              void* d_out, int out_size)
{
    const float* x      = (const float*)d_in[0];
    const float* trace  = (const float*)d_in[1];
    const int*   src_n  = (const int*)d_in[2];
    const int*   src_f  = (const int*)d_in[3];
    const float* W      = (const float*)d_in[4];
    const float* bias   = (const float*)d_in[5];
    float* out = (float*)d_out;

    transpose_kernel<<<dim3(N_ + 1, 2), 256>>>(trace, x);
    for (int l = 0; l < L_; ++l)
        layer_kernel<<<dim3(M_, B_ / BT_), 128>>>(out, src_n, src_f, W, bias, l);
}

// round 7
// speedup vs baseline: 1.1264x; 1.1264x over previous
#include <cuda_runtime.h>
#include <cstdint>
#include <cstddef>

#define L_  8
#define M_  128
#define K_  32
#define D_  16
#define B_  2048
#define N_  1024   /* L_*M_ */
#define NT_ 8      /* batch tiles of 256 */

#define XT_OFF   0u
#define TR_OFF   ((unsigned)(D_ * B_))
#define OUT_OFF  ((unsigned)(D_ * B_ + N_ * D_ * B_))

static __device__ float g_scratch[(size_t)D_ * B_ + 2ull * N_ * D_ * B_];
static __device__ int   g_ctr[L_][NT_];   // per-(layer, batch-tile) done count

// ---- packed fp32x2 helpers (sm_10x) ---------------------------------------
__device__ __forceinline__ unsigned long long fma2(
    unsigned long long a, unsigned long long b, unsigned long long c)
{
    unsigned long long d;
    asm("fma.rn.f32x2 %0, %1, %2, %3;" : "=l"(d) : "l"(a), "l"(b), "l"(c));
    return d;
}
__device__ __forceinline__ unsigned long long pack2(float lo, float hi)
{
    unsigned long long r;
    asm("mov.b64 %0, {%1, %2};" : "=l"(r) : "f"(lo), "f"(hi));
    return r;
}
__device__ __forceinline__ float2 unpack2(unsigned long long v)
{
    float2 r;
    asm("mov.b64 {%0, %1}, %2;" : "=f"(r.x), "=f"(r.y) : "l"(v));
    return r;
}

// ---------------------------------------------------------------------------
// Transpose: block = (node, half-of-B).  One (1024, D) half-tile -> (D, 1024).
// Block (0,0) also zeroes the dependency counters for the fused kernel.
// ---------------------------------------------------------------------------
__global__ void __launch_bounds__(256) transpose_kernel(
    const float* __restrict__ trace, const float* __restrict__ x)
{
    __shared__ float tile[128 * 17];
    const int blk  = blockIdx.x;
    const int half = blockIdx.y;
    const int t    = threadIdx.x;

    if (blk == 0 && half == 0 && t < L_ * NT_)
        reinterpret_cast<int*>(g_ctr)[t] = 0;

    const float* src = (blk < N_) ? (trace + (size_t)blk * B_ * D_) : x;
    float* dst = (blk < N_) ? (g_scratch + TR_OFF + (size_t)blk * D_ * B_)
                            : (g_scratch + XT_OFF);
    src += (size_t)half * (B_ / 2) * D_;

    for (int ti = 0; ti < B_ / 256; ++ti) {
        const float4* s4 = reinterpret_cast<const float4*>(src + (size_t)ti * 128 * D_);
        #pragma unroll
        for (int j = t; j < 512; j += 256) {
            float4 v = s4[j];
            int bb = j >> 2;
            int dd = (j & 3) * 4;
            tile[bb * 17 + dd + 0] = v.x;
            tile[bb * 17 + dd + 1] = v.y;
            tile[bb * 17 + dd + 2] = v.z;
            tile[bb * 17 + dd + 3] = v.w;
        }
        __syncthreads();
        #pragma unroll
        for (int j = t; j < 2048; j += 256) {
            int d  = j >> 7;
            int bb = j & 127;
            dst[(size_t)d * B_ + half * (B_ / 2) + ti * 128 + bb] = tile[bb * 17 + d];
        }
        __syncthreads();
    }
}

// ---------------------------------------------------------------------------
// Fused kernel: ALL 8 layers in one launch.
// block = (node m = blockIdx.x, batch-tile j = blockIdx.y, layer l = blockIdx.z)
// bid order is layer-major, so dependency blocks always have smaller bids.
// A layer-l block waits (release/acquire) for the 128 node-blocks of
// (l-1, same tile j); prologue loads run before the wait.
// Compute core = R3 (2 batches/thread, fp32x2 d-pair, gathers in chunks of 8).
// ---------------------------------------------------------------------------
__global__ void __launch_bounds__(128, 8) fused_layers(
    float* __restrict__ out,
    const int* __restrict__ src_node,
    const int* __restrict__ src_feat,
    const float* __restrict__ W,
    const float* __restrict__ bias)
{
    const int m = blockIdx.x;
    const int j = blockIdx.y;
    const int l = blockIdx.z;
    const int n = l * M_ + m;
    const int t = threadIdx.x;
    const int b = (j * 128 + t) * 2;            // batch pair within tile j

    __shared__ float    sWt[K_ * D_];           // sWt[k*16 + d] = W[n][d][k]
    __shared__ float    sBias[D_];
    __shared__ unsigned sOff[K_];

    // ---- prologue: independent of cross-layer deps -------------------------
    #pragma unroll
    for (int i = t; i < D_ * K_; i += 128) {
        int d = i >> 5, k = i & 31;
        sWt[k * D_ + d] = W[(size_t)n * (D_ * K_) + i];
    }
    if (t < D_) sBias[t] = bias[n * D_ + t];
    if (t < K_) {
        int sn = src_node[n * K_ + t];
        int sf = src_feat[n * K_ + t];
        unsigned off;
        if (sn == 0) {
            off = XT_OFF + (unsigned)sf * B_;
        } else if (sn <= l * M_) {
            off = OUT_OFF + ((unsigned)(sn - 1) * D_ + (unsigned)sf) * B_;
        } else {
            off = TR_OFF  + ((unsigned)(sn - 1) * D_ + (unsigned)sf) * B_;
        }
        sOff[t] = off;
    }
    __syncthreads();

    // ---- dependency wait: tile j of layer l-1 fully written ---------------
    if (l > 0) {
        if (t == 0) {
            const int* p = &g_ctr[l - 1][j];
            int v;
            for (;;) {
                asm volatile("ld.acquire.gpu.s32 %0, [%1];"
                             : "=r"(v) : "l"(p) : "memory");
                if (v >= M_) break;
                __nanosleep(128);
            }
        }
        __syncthreads();
    }

    // ---- compute: R3 core --------------------------------------------------
    unsigned long long accx[D_ / 2], accy[D_ / 2];
    #pragma unroll
    for (int dp = 0; dp < D_ / 2; ++dp) {
        unsigned long long bp = pack2(sBias[2 * dp], sBias[2 * dp + 1]);
        accx[dp] = bp;
        accy[dp] = bp;
    }

    #pragma unroll
    for (int kc = 0; kc < K_ / 8; ++kc) {
        float2 g[8];
        #pragma unroll
        for (int jj = 0; jj < 8; ++jj)
            g[jj] = *reinterpret_cast<const float2*>(
                &g_scratch[sOff[8 * kc + jj] + (unsigned)b]);

        #pragma unroll
        for (int jj = 0; jj < 8; ++jj) {
            const int k = 8 * kc + jj;
            unsigned long long gx = pack2(g[jj].x, g[jj].x);
            unsigned long long gy = pack2(g[jj].y, g[jj].y);
            const ulonglong2* wrow = reinterpret_cast<const ulonglong2*>(&sWt[k * D_]);
            #pragma unroll
            for (int q = 0; q < 4; ++q) {
                ulonglong2 w2 = wrow[q];
                accx[2 * q + 0] = fma2(gx, w2.x, accx[2 * q + 0]);
                accx[2 * q + 1] = fma2(gx, w2.y, accx[2 * q + 1]);
                accy[2 * q + 0] = fma2(gy, w2.x, accy[2 * q + 0]);
                accy[2 * q + 1] = fma2(gy, w2.y, accy[2 * q + 1]);
            }
        }
    }

    float ax[D_], ay[D_];
    #pragma unroll
    for (int dp = 0; dp < D_ / 2; ++dp) {
        float2 vx = unpack2(accx[dp]), vy = unpack2(accy[dp]);
        ax[2 * dp]     = fmaxf(vx.x, 0.0f);
        ax[2 * dp + 1] = fmaxf(vx.y, 0.0f);
        ay[2 * dp]     = fmaxf(vy.x, 0.0f);
        ay[2 * dp + 1] = fmaxf(vy.y, 0.0f);
    }

    // Transposed copy for later-layer gathers (skip on last layer).
    if (l != L_ - 1) {
        float* oT = g_scratch + OUT_OFF + (size_t)n * (D_ * B_);
        #pragma unroll
        for (int d = 0; d < D_; ++d)
            *reinterpret_cast<float2*>(&oT[d * B_ + b]) = make_float2(ax[d], ay[d]);
    }

    // Final output (N, B, D).
    float* o = out + ((size_t)n * B_ + (size_t)b) * D_;
    #pragma unroll
    for (int d4 = 0; d4 < D_ / 4; ++d4) {
        *reinterpret_cast<float4*>(&o[4 * d4]) =
            make_float4(ax[4 * d4 + 0], ax[4 * d4 + 1], ax[4 * d4 + 2], ax[4 * d4 + 3]);
        *reinterpret_cast<float4*>(&o[D_ + 4 * d4]) =
            make_float4(ay[4 * d4 + 0], ay[4 * d4 + 1], ay[4 * d4 + 2], ay[4 * d4 + 3]);
    }

    // ---- signal: release this (layer, tile) -------------------------------
    if (l != L_ - 1) {
        __threadfence();            // make outT writes GPU-visible
        __syncthreads();            // all threads' stores + fences done
        if (t == 0) atomicAdd(&g_ctr[l][j], 1);
    }
}

extern "C" void kernel_launch(void* const* d_in, const int* in_sizes, int n_in,
                              void* d_out, int out_size)
{
    const float* x      = (const float*)d_in[0];
    const float* trace  = (const float*)d_in[1];
    const int*   src_n  = (const int*)d_in[2];
    const int*   src_f  = (const int*)d_in[3];
    const float* W      = (const float*)d_in[4];
    const float* bias   = (const float*)d_in[5];
    float* out = (float*)d_out;

    transpose_kernel<<<dim3(N_ + 1, 2), 256>>>(trace, x);
    fused_layers<<<dim3(M_, NT_, L_), 128>>>(out, src_n, src_f, W, bias);
}